// round 9
// baseline (speedup 1.0000x reference)
#include <cuda_runtime.h>
#include <mma.h>
#include <math.h>

// ============================================================================
// SphericalHarmonicsShellsConv — GB300 (sm_103a)   Round 8
//   Tensor-core GEMM (wmma tf32 split hi/lo) + smem-staged gather + epilogue
//   B=4, N=4096, V=2048, P=32, C=16
// Signal channel layout (concat, 256 cols):
//   l=0: [0,16) rowlen16 | l=1: [16,64) rowlen48 | l=2: [64,144) rowlen80
//   l=3: [144,256) rowlen112
// y rows (30, padded to 32): yoff={0,4,13,23}; row = yoff[j] + n*(4-j) + i
// Outputs: out[J] shape (B,V,2J+1,chJ), chJ={160,336,384,320}
// ============================================================================

#define B_ 4
#define N_ 4096
#define V_ 2048
#define P_ 32
#define BV_ (B_*V_)

#define NGROUPS 333          // 5328 output elements / 16 channels
#define MAXNNZ 64            // max CG pairs per group (<=50 incl. pad)
#define YS 264               // ysm/gsm row stride in floats (16B-aligned rows)

// pair: {coef, ybase} packed as float2 (y = bitcast int ybase)
__device__ float2 g_pairs[NGROUPS * MAXNNZ];
__device__ int2   g_meta[NGROUPS];     // x = (J<<16)|local_base, y = nnz (even)
__device__ float  d_cg[27 * 343];      // dense real CG tables, stride 343/combo

// ---------------------------------------------------------------------------
// combo <-> (j,l,J) mapping
// ---------------------------------------------------------------------------
__device__ __forceinline__ void combo_decode(int combo, int& j, int& l, int& J) {
    j = -1;
    int idx = 0;
    for (int jj = 1; jj <= 3; jj++)
        for (int ll = 1; ll <= 3; ll++) {
            int lo = abs(jj - ll), hi = min(jj + ll, 3);
            for (int JJ = lo; JJ <= hi; JJ++) {
                if (idx == combo) { j = jj; l = ll; J = JJ; return; }
                idx++;
            }
        }
}

__device__ __forceinline__ int combo_index(int j, int l, int J) {
    int idx = 0;
    for (int jj = 1; jj <= 3; jj++)
        for (int ll = 1; ll <= 3; ll++) {
            int lo = abs(jj - ll), hi = min(jj + ll, 3);
            for (int JJ = lo; JJ <= hi; JJ++) {
                if (jj == j && ll == l && JJ == J) return idx;
                idx++;
            }
        }
    return -1;
}

// ---------------------------------------------------------------------------
// su2 CG in fp32 (all factorials <= 10! < 2^24, exact in fp32)
// ---------------------------------------------------------------------------
__device__ __forceinline__ float ffact(int n) {
    const float f[11] = {1.f,1.f,2.f,6.f,24.f,120.f,720.f,5040.f,40320.f,
                         362880.f,3628800.f};
    return f[n];
}

__device__ float su2_cg_f(int j1,int m1,int j2,int m2,int j3,int m3) {
    if (m3 != m1 + m2) return 0.0f;
    int vmin = max(max(-j1 + j2 + m3, -j1 + m1), 0);
    int vmax = min(min(j2 + j3 + m1, j3 - j1 + j2), j3 + m3);
    float C = sqrtf((2.f*j3 + 1.f) * ffact(j3+j1-j2) * ffact(j3-j1+j2) * ffact(j1+j2-j3)
                    * ffact(j3+m3) * ffact(j3-m3)
                    / (ffact(j1+j2+j3+1) * ffact(j1-m1) * ffact(j1+m1)
                       * ffact(j2-m2) * ffact(j2+m2)));
    float S = 0.0f;
    for (int v = vmin; v <= vmax; v++) {
        float sgn = ((v + j2 + m2) & 1) ? -1.0f : 1.0f;
        S += sgn * ffact(j2+j3+m1-v) * ffact(j1-m1+v)
             / (ffact(v) * ffact(j3-j1+j2-v) * ffact(j3+m3-v) * ffact(v+j1-j2-m3));
    }
    return C * S;
}

// Q = (-i)^l * q_real_to_complex(l); entry (r, c)
__device__ void qmat_f(int l, int r, int c, float& re, float& im) {
    const float s2 = 0.70710678118654752f;
    int m = r - l;
    float qr = 0.0f, qi = 0.0f;
    if (m < 0) {
        if (c == l - m)      qr =  s2;
        else if (c == l + m) qi = -s2;
    } else if (m == 0) {
        if (c == l) qr = 1.0f;
    } else {
        float sgn = (m & 1) ? -1.0f : 1.0f;
        if (c == l + m)      qr = sgn * s2;
        else if (c == l - m) qi = sgn * s2;
    }
    switch (l & 3) {
        case 0: re =  qr; im =  qi; break;
        case 1: re =  qi; im = -qr; break;
        case 2: re = -qr; im = -qi; break;
        default: re = -qi; im =  qr; break;
    }
}

// ---------------------------------------------------------------------------
// Init 1: fused su2 + basis change — one CTA per combo
// ---------------------------------------------------------------------------
__global__ void init_cg_kernel() {
    __shared__ float su2_sm[49];
    int combo = blockIdx.x;
    int e     = threadIdx.x;

    int j, l, J;
    combo_decode(combo, j, l, J);
    int dl = 2*l + 1, dJ = 2*J + 1, dj = 2*j + 1;

    if (e < 49) {
        int i = e / 7, k = e % 7;
        float v = 0.0f;
        if (i < dj && k < dl) {
            int m1 = i - j, m2 = k - l, m3 = m1 + m2;
            if (m3 >= -J && m3 <= J)
                v = su2_cg_f(j, m1, l, m2, J, m3);
        }
        su2_sm[e] = v;
    }
    __syncthreads();

    if (e >= 343) return;
    int tot = dj * dl * dJ;
    if (e >= tot) { d_cg[combo * 343 + e] = 0.0f; return; }

    int pp  = e % dJ;
    int rem = e / dJ;
    int b   = rem % dl;
    int a   = rem / dl;

    float accR = 0.0f;
    for (int i = 0; i < dj; i++) {
        float q1r, q1i; qmat_f(j, i, a, q1r, q1i);
        if (q1r == 0.0f && q1i == 0.0f) continue;
        int m1 = i - j;
        for (int k = 0; k < dl; k++) {
            int m2 = k - l, m3 = m1 + m2;
            if (m3 < -J || m3 > J) continue;
            float q2r, q2i; qmat_f(l, k, b, q2r, q2i);
            if (q2r == 0.0f && q2i == 0.0f) continue;
            float s = su2_sm[i * 7 + k];
            if (s == 0.0f) continue;
            float q3r, q3i; qmat_f(J, J + m3, pp, q3r, q3i);
            q3i = -q3i;   // conj
            float tr = q1r*q2r - q1i*q2i, ti = q1r*q2i + q1i*q2r;
            accR += (tr*q3r - ti*q3i) * s;
        }
    }
    d_cg[combo * 343 + e] = accR;
}

// ---------------------------------------------------------------------------
// Init 2: build the 333-group sparse program (nnz padded to even)
//   ybase offsets use the YS=264 row stride
// ---------------------------------------------------------------------------
struct Seg { signed char type, j, l; short cstart; };  // 0=D0(l=0),1=D1(j=0),2=CG,-1=end

__global__ void init_prog_kernel() {
    int g = blockIdx.x * blockDim.x + threadIdx.x;
    if (g >= NGROUPS) return;

    const int gcum[5]    = {0, 10, 73, 193, 333};
    const int gperrow[4] = {10, 21, 24, 20};
    const int chJ[4]     = {160, 336, 384, 320};
    const int yoff[4]    = {0, 4, 13, 23};
    const int coff[4]    = {0, 16, 64, 144};

    const Seg segJ0[] = {{0,0,0,0},{2,1,1,64},{2,2,2,112},{2,3,3,144},{-1,0,0,160}};
    const Seg segJ1[] = {{0,1,0,0},{1,0,1,48},{2,1,1,112},{2,2,1,160},{2,1,2,192},
                         {2,2,2,240},{2,3,2,272},{2,2,3,288},{2,3,3,320},{-1,0,0,336}};
    const Seg segJ2[] = {{0,2,0,0},{1,0,2,32},{2,1,1,96},{2,2,1,144},{2,3,1,176},
                         {2,1,2,192},{2,2,2,240},{2,3,2,272},{2,1,3,288},{2,2,3,336},
                         {2,3,3,368},{-1,0,0,384}};
    const Seg segJ3[] = {{0,3,0,0},{1,0,3,16},{2,2,1,80},{2,3,1,112},{2,1,2,128},
                         {2,2,2,176},{2,3,2,208},{2,1,3,224},{2,2,3,272},{2,3,3,304},
                         {-1,0,0,320}};
    const Seg* segs[4] = {segJ0, segJ1, segJ2, segJ3};

    int J  = (g < 10) ? 0 : (g < 73) ? 1 : (g < 193) ? 2 : 3;
    int rl = g - gcum[J];
    int p  = rl / gperrow[J];
    int c  = (rl % gperrow[J]) * 16;

    const Seg* st = segs[J];
    int si = 0;
    while (st[si + 1].type != -1 && st[si + 1].cstart <= c) si++;
    Seg sg = st[si];
    int cl = c - sg.cstart;
    int i  = cl >> 4;

    float2* out = &g_pairs[g * MAXNNZ];
    int n = 0;
    if (sg.type == 0) {              // l=0 direct, j=J
        out[n].x = 1.0f;
        out[n].y = __int_as_float((yoff[J] + p * (4 - J) + i) * YS);
        n++;
    } else if (sg.type == 1) {       // j=0 direct, l=J
        out[n].x = 1.0f;
        out[n].y = __int_as_float(i * YS + coff[J] + p * 16);
        n++;
    } else {                         // CG contraction
        int j = sg.j, l = sg.l;
        int cb = combo_index(j, l, J) * 343;
        int dl = 2*l + 1, dJ = 2*J + 1;
        for (int nn = 0; nn < 2*j + 1; nn++)
            for (int m = 0; m < dl; m++) {
                float coef = d_cg[cb + (nn * dl + m) * dJ + p];
                if (fabsf(coef) > 1e-6f) {
                    out[n].x = coef;
                    out[n].y = __int_as_float((yoff[j] + nn * (4 - j) + i) * YS
                                              + coff[l] + m * 16);
                    n++;
                }
            }
    }
    if (n & 1) {                     // pad to even for float4 streaming
        out[n].x = 0.0f;
        out[n].y = __int_as_float(0);
        n++;
    }
    g_meta[g] = make_int2((J << 16) | (p * chJ[J] + c), n);
}

// ---------------------------------------------------------------------------
// Main kernel: one CTA (256 threads) per (b,v)
//   gather -> smem, wmma tf32 split-precision GEMM, y in smem, CG epilogue
// ---------------------------------------------------------------------------
using namespace nvcuda;

__global__ __launch_bounds__(256, 3)
void conv_kernel(const float* __restrict__ x0, const float* __restrict__ x1,
                 const float* __restrict__ x2, const float* __restrict__ x3,
                 const int*   __restrict__ patches,
                 const float* __restrict__ kernels,
                 float* __restrict__ out)
{
    __shared__ __align__(16) float A_sm[32 * 32];      // A[y][p] = K[p][y], rows 30,31 = 0
    __shared__ __align__(16) float gsm[32 * YS];       // g[p][ch]; later y[yrow][ch]
    __shared__ int rowIdx[32];

    const int bv  = blockIdx.x;
    const int tid = threadIdx.x;

    // stage A = K^T (consecutive tid -> consecutive p: coalesced STS)
    const float* kp = kernels + (size_t)bv * (P_ * 30);
    for (int t = tid; t < 32 * 32; t += 256) {
        int y = t >> 5, p = t & 31;
        A_sm[y * 32 + p] = (y < 30) ? kp[p * 30 + y] : 0.0f;
    }
    if (tid < P_) {
        int2 pi = ((const int2*)patches)[(size_t)bv * P_ + tid];
        rowIdx[tid] = pi.x * N_ + pi.y;
    }

    // column -> source decode (thread owns channel column tid)
    const float* xb; int rowlen, cloc;
    if (tid < 16)       { xb = x0; rowlen = 16;  cloc = tid;       }
    else if (tid < 64)  { xb = x1; rowlen = 48;  cloc = tid - 16;  }
    else if (tid < 144) { xb = x2; rowlen = 80;  cloc = tid - 64;  }
    else                { xb = x3; rowlen = 112; cloc = tid - 144; }

    __syncthreads();

    // gather g[p][tid] from global (L2 hits), coalesced STS per row
    #pragma unroll 8
    for (int p = 0; p < P_; p++)
        gsm[p * YS + tid] = __ldg(xb + (long)rowIdx[p] * rowlen + cloc);
    __syncthreads();

    // ---- wmma tf32 GEMM: C[32,256] = A[32,32] @ g[32,256], split hi/lo ----
    const int warpId = tid >> 5;
    const int mt  = warpId & 1;            // m-tile 0/1
    const int nt0 = (warpId >> 1) << 2;    // 4 n-tiles per warp

    wmma::fragment<wmma::accumulator, 16, 16, 8, float> acc[4];
    #pragma unroll
    for (int t = 0; t < 4; t++) wmma::fill_fragment(acc[t], 0.0f);

    #pragma unroll
    for (int k = 0; k < 4; k++) {
        wmma::fragment<wmma::matrix_a, 16, 16, 8, wmma::precision::tf32,
                       wmma::row_major> ar, ah, al;
        wmma::load_matrix_sync(ar, A_sm + mt * 16 * 32 + k * 8, 32);
        #pragma unroll
        for (int i = 0; i < ar.num_elements; i++) {
            float v = ar.x[i];
            float h = wmma::__float_to_tf32(v);
            ah.x[i] = h;
            al.x[i] = wmma::__float_to_tf32(v - h);
        }
        #pragma unroll
        for (int t = 0; t < 4; t++) {
            wmma::fragment<wmma::matrix_b, 16, 16, 8, wmma::precision::tf32,
                           wmma::row_major> br, bh, bl;
            wmma::load_matrix_sync(br, gsm + k * 8 * YS + (nt0 + t) * 16, YS);
            #pragma unroll
            for (int i = 0; i < br.num_elements; i++) {
                float v = br.x[i];
                float h = wmma::__float_to_tf32(v);
                bh.x[i] = h;
                bl.x[i] = wmma::__float_to_tf32(v - h);
            }
            wmma::mma_sync(acc[t], ah, bh, acc[t]);
            wmma::mma_sync(acc[t], al, bh, acc[t]);
            wmma::mma_sync(acc[t], ah, bl, acc[t]);
        }
    }
    __syncthreads();   // all B reads done -> safe to overwrite gsm with y
    #pragma unroll
    for (int t = 0; t < 4; t++)
        wmma::store_matrix_sync(gsm + mt * 16 * YS + (nt0 + t) * 16, acc[t],
                                YS, wmma::mem_row_major);
    __syncthreads();

    // ---- epilogue: 333 groups x 4 quarters; 2 coefficient pairs per 16B ----
    const size_t outBase[4] = {0, 1310720, 9568256, 25296896};
    const int    slab[4]    = {160, 1008, 1920, 2240};

    for (int item = tid; item < NGROUPS * 4; item += 256) {
        int g = item >> 2, q = item & 3;
        int2 gm = g_meta[g];
        int nnz = gm.y;                            // even
        const float4* pr4 = (const float4*)&g_pairs[g * MAXNNZ];
        const float* ybase = gsm + q * 4;
        float4 a = make_float4(0.f, 0.f, 0.f, 0.f);
        for (int k = 0; k < nnz; k += 2) {
            float4 rec = pr4[k >> 1];              // {c0, yb0, c1, yb1}
            const float4 v0 = *(const float4*)&ybase[__float_as_int(rec.y)];
            const float4 v1 = *(const float4*)&ybase[__float_as_int(rec.w)];
            a.x = fmaf(rec.x, v0.x, a.x);
            a.y = fmaf(rec.x, v0.y, a.y);
            a.z = fmaf(rec.x, v0.z, a.z);
            a.w = fmaf(rec.x, v0.w, a.w);
            a.x = fmaf(rec.z, v1.x, a.x);
            a.y = fmaf(rec.z, v1.y, a.y);
            a.z = fmaf(rec.z, v1.z, a.z);
            a.w = fmaf(rec.z, v1.w, a.w);
        }
        int J = gm.x >> 16;
        int local = gm.x & 0xffff;
        size_t off = outBase[J] + (size_t)bv * slab[J] + local + q * 4;
        *(float4*)&out[off] = a;
    }
}

// ---------------------------------------------------------------------------
extern "C" void kernel_launch(void* const* d_in, const int* in_sizes, int n_in,
                              void* d_out, int out_size) {
    const float* x0      = (const float*)d_in[0];
    const float* x1      = (const float*)d_in[1];
    const float* x2      = (const float*)d_in[2];
    const float* x3      = (const float*)d_in[3];
    const int*   patches = (const int*)d_in[4];
    const float* kernels = (const float*)d_in[5];
    float*       out     = (float*)d_out;

    init_cg_kernel<<<27, 352>>>();
    init_prog_kernel<<<3, 128>>>();
    conv_kernel<<<BV_, 256>>>(x0, x1, x2, x3, patches, kernels, out);
}